// round 6
// baseline (speedup 1.0000x reference)
#include <cuda_runtime.h>

// Depthwise 3x3 conv, stride 1, VALID, fp32.
// x: (16, 64, 512, 512), weight: (64, 3, 3), out: (16, 64, 510, 510)

#define CCH    64
#define HH     512
#define WW     512
#define OHT    510
#define OWD    510
#define ROWS   30     // output rows per CTA (17 * 30 = 510)
#define NTILES 17

__device__ __forceinline__ float conv1d3(const float v[6], int j,
                                         float w0, float w1, float w2, float s)
{
    s = fmaf(v[j],     w0, s);
    s = fmaf(v[j + 1], w1, s);
    s = fmaf(v[j + 2], w2, s);
    return s;
}

__global__ __launch_bounds__(128, 10)
void dwconv3x3_kernel(const float* __restrict__ x,
                      const float* __restrict__ wgt,
                      float* __restrict__ out)
{
    const int tile = blockIdx.x;          // 0..16 (fast-varying: same-plane tiles co-resident)
    const int nc   = blockIdx.y;          // n*64 + c
    const int c    = nc & (CCH - 1);

    const float* xp = x   + (size_t)nc * HH * WW;
    float*       op = out + (size_t)nc * OHT * OWD;

    float wt[9];
#pragma unroll
    for (int i = 0; i < 9; i++) wt[i] = __ldg(wgt + c * 9 + i);

    const int  tid   = threadIdx.x;       // 0..127
    const int  x0    = tid * 4;           // output cols x0..x0+3
    const bool hi_ok = (tid < 127);       // tid 127: halo/upper outputs OOB
    const int  y0    = tile * ROWS;

    // 4-row register window: rows y..y+3 (float4 body + float2 halo each).
    float4 a0, a1, a2, a3;
    float2 b0, b1, b2, b3;
    {
        const float* r = xp + (size_t)y0 * WW + x0;
        a0 = *(const float4*)(r);
        a1 = *(const float4*)(r + WW);
        a2 = *(const float4*)(r + 2 * WW);
        a3 = *(const float4*)(r + 3 * WW);
        if (hi_ok) {
            b0 = *(const float2*)(r + 4);
            b1 = *(const float2*)(r + WW + 4);
            b2 = *(const float2*)(r + 2 * WW + 4);
            b3 = *(const float2*)(r + 3 * WW + 4);
        } else {
            b0 = b1 = b2 = b3 = make_float2(0.f, 0.f);
        }
    }

    // Prefetch pointers: rows y0+4, y0+5 for the next iteration (clamped).
    const float* rp      = xp + (size_t)(y0 + 4) * WW + x0;
    const float* rp_last = xp + (size_t)(HH - 1) * WW + x0;

#pragma unroll 1
    for (int yy = 0; yy < ROWS; yy += 2) {
        // ---- prefetch 2 rows (batched: MLP_p1 = 4), consumed NEXT iteration ----
        const float* r4 = (rp      > rp_last) ? rp_last : rp;
        const float* r5 = (rp + WW > rp_last) ? rp_last : rp + WW;
        float4 pa0 = *(const float4*)r4;
        float4 pa1 = *(const float4*)r5;
        float2 pb0 = hi_ok ? *(const float2*)(r4 + 4) : make_float2(0.f, 0.f);
        float2 pb1 = hi_ok ? *(const float2*)(r5 + 4) : make_float2(0.f, 0.f);
        rp += 2 * WW;

        // ---- compute output rows yy, yy+1 from resident rows ----
        const float v0[6] = {a0.x, a0.y, a0.z, a0.w, b0.x, b0.y};
        const float v1[6] = {a1.x, a1.y, a1.z, a1.w, b1.x, b1.y};
        const float v2[6] = {a2.x, a2.y, a2.z, a2.w, b2.x, b2.y};
        const float v3[6] = {a3.x, a3.y, a3.z, a3.w, b3.x, b3.y};

        float acc0[4], acc1[4];
#pragma unroll
        for (int j = 0; j < 4; j++) {
            float s0 = v0[j] * wt[0];
            s0 = fmaf(v0[j + 1], wt[1], s0);
            s0 = fmaf(v0[j + 2], wt[2], s0);
            s0 = conv1d3(v1, j, wt[3], wt[4], wt[5], s0);
            s0 = conv1d3(v2, j, wt[6], wt[7], wt[8], s0);
            acc0[j] = s0;

            float s1 = v1[j] * wt[0];
            s1 = fmaf(v1[j + 1], wt[1], s1);
            s1 = fmaf(v1[j + 2], wt[2], s1);
            s1 = conv1d3(v2, j, wt[3], wt[4], wt[5], s1);
            s1 = conv1d3(v3, j, wt[6], wt[7], wt[8], s1);
            acc1[j] = s1;
        }

        // ---- stores: rows always 8B-aligned (2040B stride) -> STG.64 streaming ----
        float* orow0 = op + (size_t)(y0 + yy) * OWD + x0;
        float* orow1 = orow0 + OWD;
        __stcs((float2*)orow0, make_float2(acc0[0], acc0[1]));
        __stcs((float2*)orow1, make_float2(acc1[0], acc1[1]));
        if (hi_ok) {                            // tid 127: cols 510/511 are OOB
            __stcs((float2*)(orow0 + 2), make_float2(acc0[2], acc0[3]));
            __stcs((float2*)(orow1 + 2), make_float2(acc1[2], acc1[3]));
        }

        // ---- rotate window by 2 rows ----
        a0 = a2; b0 = b2;
        a1 = a3; b1 = b3;
        a2 = pa0; b2 = pb0;
        a3 = pa1; b3 = pb1;
    }
}

extern "C" void kernel_launch(void* const* d_in, const int* in_sizes, int n_in,
                              void* d_out, int out_size)
{
    const float* x   = (const float*)d_in[0];
    const float* wgt = (const float*)d_in[1];
    float*       out = (float*)d_out;

    dim3 grid(NTILES, 16 * CCH);   // 17 row tiles (fast) x 1024 (n,c) planes
    dwconv3x3_kernel<<<grid, 128>>>(x, wgt, out);
}